// round 1
// baseline (speedup 1.0000x reference)
#include <cuda_runtime.h>

#define C_DIM 256
#define BD    128
#define SS    784
#define SSP   800   // padded row stride for scratch (3200 B, 128B-aligned)
#define CN    128
#define ALPHA 32.0f

// LayerNormed + transposed x: [C][BD][SSP]  (~105 MB static scratch)
__device__ float g_xre[(size_t)C_DIM * BD * SSP];

// ---------------------------------------------------------------------------
// Kernel 1: LayerNorm over C (last dim) + transpose to [C][BD][SS] scratch.
// One block = (bd, tile of 32 hw positions). 256 threads / 8 warps.
// ---------------------------------------------------------------------------
__global__ void ln_transpose_kernel(const float* __restrict__ x,
                                    const float* __restrict__ lnw,
                                    const float* __restrict__ lnb) {
    __shared__ float s[32][C_DIM + 1];   // pitch 257 -> conflict-free column reads
    int bd   = blockIdx.x;
    int hw0  = blockIdx.y * 32;
    int lane = threadIdx.x & 31;
    int warp = threadIdx.x >> 5;

    // Each warp handles 4 positions: full 256-ch row per position.
    #pragma unroll
    for (int i = 0; i < 4; i++) {
        int p  = warp * 4 + i;
        int hw = hw0 + p;
        if (hw < SS) {
            const float4* row = (const float4*)(x + ((size_t)bd * SS + hw) * C_DIM);
            float4 v0 = row[lane];        // c = 4*lane
            float4 v1 = row[lane + 32];   // c = 128 + 4*lane
            float s1 = v0.x + v0.y + v0.z + v0.w + v1.x + v1.y + v1.z + v1.w;
            float s2 = v0.x*v0.x + v0.y*v0.y + v0.z*v0.z + v0.w*v0.w
                     + v1.x*v1.x + v1.y*v1.y + v1.z*v1.z + v1.w*v1.w;
            #pragma unroll
            for (int o = 16; o > 0; o >>= 1) {
                s1 += __shfl_xor_sync(0xffffffffu, s1, o);
                s2 += __shfl_xor_sync(0xffffffffu, s2, o);
            }
            float mean = s1 * (1.0f / C_DIM);
            float var  = s2 * (1.0f / C_DIM) - mean * mean;
            float rs   = rsqrtf(var + 1e-5f);
            int c0 = lane * 4;
            int c1 = 128 + lane * 4;
            s[p][c0+0] = (v0.x - mean) * rs * lnw[c0+0] + lnb[c0+0];
            s[p][c0+1] = (v0.y - mean) * rs * lnw[c0+1] + lnb[c0+1];
            s[p][c0+2] = (v0.z - mean) * rs * lnw[c0+2] + lnb[c0+2];
            s[p][c0+3] = (v0.w - mean) * rs * lnw[c0+3] + lnb[c0+3];
            s[p][c1+0] = (v1.x - mean) * rs * lnw[c1+0] + lnb[c1+0];
            s[p][c1+1] = (v1.y - mean) * rs * lnw[c1+1] + lnb[c1+1];
            s[p][c1+2] = (v1.z - mean) * rs * lnw[c1+2] + lnb[c1+2];
            s[p][c1+3] = (v1.w - mean) * rs * lnw[c1+3] + lnb[c1+3];
        }
    }
    __syncthreads();

    // Write phase: warp w owns channels [w*32, w*32+32); lane = hw offset.
    int nhw = min(32, SS - hw0);
    #pragma unroll
    for (int j = 0; j < 32; j++) {
        int c = warp * 32 + j;
        if (lane < nhw)
            g_xre[(size_t)c * (BD * SSP) + (size_t)bd * SSP + hw0 + lane] = s[lane][c];
    }
}

// ---------------------------------------------------------------------------
// Kernel 2: batched distance GEMM + sqrt epilogue.
// One block per c (256 blocks). Computes full 128x128 tile, K = 784.
// 256 threads, 8x8 register tile each. Row norms of A and B accumulated
// during the tile loads (each element loaded exactly once per block).
// mode 0: A = g_xre (lda=SSP), B = cluster_center; out[(m*C + c)*CN + n]
// mode 1: A = B = cluster_center;                 out[c*CN*CN + m*CN + n]
// ---------------------------------------------------------------------------
__global__ void __launch_bounds__(256, 2)
dist_gemm_kernel(const float* __restrict__ Bglob, float* __restrict__ out, int mode) {
    __shared__ float As[16][132];   // pitch 132 (528 B, 16B-aligned rows)
    __shared__ float Bs[16][132];
    __shared__ float sAn[128];
    __shared__ float sBn[128];

    int c = blockIdx.x;
    const float* Ab;
    size_t lda;
    if (mode == 0) { Ab = g_xre + (size_t)c * BD * SSP; lda = SSP; }
    else           { Ab = Bglob + (size_t)c * CN * SS;  lda = SS;  }
    const float* Bb = Bglob + (size_t)c * CN * SS;

    int t  = threadIdx.x;
    int tx = t & 15, ty = t >> 4;
    int lm = t >> 1;             // load row (2 threads per row)
    int lk = (t & 1) * 8;        // k offset within 16-wide tile

    const float* Arow = Ab + (size_t)lm * lda + lk;
    const float* Brow = Bb + (size_t)lm * SS  + lk;

    float acc[8][8];
    #pragma unroll
    for (int i = 0; i < 8; i++)
        #pragma unroll
        for (int j = 0; j < 8; j++) acc[i][j] = 0.0f;
    float an = 0.0f, bn = 0.0f;

    for (int k0 = 0; k0 < SS; k0 += 16) {
        float4 a0 = *(const float4*)(Arow + k0);
        float4 a1 = *(const float4*)(Arow + k0 + 4);
        float4 b0 = *(const float4*)(Brow + k0);
        float4 b1 = *(const float4*)(Brow + k0 + 4);

        an += a0.x*a0.x + a0.y*a0.y + a0.z*a0.z + a0.w*a0.w
            + a1.x*a1.x + a1.y*a1.y + a1.z*a1.z + a1.w*a1.w;
        bn += b0.x*b0.x + b0.y*b0.y + b0.z*b0.z + b0.w*b0.w
            + b1.x*b1.x + b1.y*b1.y + b1.z*b1.z + b1.w*b1.w;

        As[lk+0][lm] = a0.x; As[lk+1][lm] = a0.y; As[lk+2][lm] = a0.z; As[lk+3][lm] = a0.w;
        As[lk+4][lm] = a1.x; As[lk+5][lm] = a1.y; As[lk+6][lm] = a1.z; As[lk+7][lm] = a1.w;
        Bs[lk+0][lm] = b0.x; Bs[lk+1][lm] = b0.y; Bs[lk+2][lm] = b0.z; Bs[lk+3][lm] = b0.w;
        Bs[lk+4][lm] = b1.x; Bs[lk+5][lm] = b1.y; Bs[lk+6][lm] = b1.z; Bs[lk+7][lm] = b1.w;
        __syncthreads();

        #pragma unroll
        for (int kk = 0; kk < 16; kk++) {
            float a[8], b[8];
            *(float4*)&a[0] = *(const float4*)&As[kk][ty * 8];
            *(float4*)&a[4] = *(const float4*)&As[kk][ty * 8 + 4];
            *(float4*)&b[0] = *(const float4*)&Bs[kk][tx * 8];
            *(float4*)&b[4] = *(const float4*)&Bs[kk][tx * 8 + 4];
            #pragma unroll
            for (int im = 0; im < 8; im++)
                #pragma unroll
                for (int in = 0; in < 8; in++)
                    acc[im][in] = fmaf(a[im], b[in], acc[im][in]);
        }
        __syncthreads();
    }

    // Row-norm reduce: threads t and t^1 share row lm.
    an += __shfl_xor_sync(0xffffffffu, an, 1);
    bn += __shfl_xor_sync(0xffffffffu, bn, 1);
    if ((t & 1) == 0) { sAn[lm] = an; sBn[lm] = bn; }
    __syncthreads();

    // Epilogue: d = sqrt(max(|a|^2 + |b|^2 - 2ab, 1e-12))
    #pragma unroll
    for (int im = 0; im < 8; im++) {
        int m = ty * 8 + im;
        float am = sAn[m];
        float r[8];
        #pragma unroll
        for (int in = 0; in < 8; in++) {
            int n = tx * 8 + in;
            float d2 = am + sBn[n] - 2.0f * acc[im][in];
            r[in] = sqrtf(fmaxf(d2, 1e-12f));
        }
        float* dst = (mode == 0)
            ? out + (size_t)m * (C_DIM * CN) + (size_t)c * CN + tx * 8
            : out + (size_t)c * (CN * CN) + (size_t)m * CN + tx * 8;
        *(float4*)dst       = make_float4(r[0], r[1], r[2], r[3]);
        *((float4*)dst + 1) = make_float4(r[4], r[5], r[6], r[7]);
    }
}

// ---------------------------------------------------------------------------
// Kernel 3: softmax(-ALPHA * d) over last dim (rows of 128). 1 warp / row.
// ---------------------------------------------------------------------------
__global__ void softmax_kernel(const float* __restrict__ din, float* __restrict__ dout) {
    int r    = blockIdx.x * 8 + (threadIdx.x >> 5);
    int lane = threadIdx.x & 31;
    const float4* row = (const float4*)(din + (size_t)r * CN);
    float4 v = row[lane];
    float mn = fminf(fminf(v.x, v.y), fminf(v.z, v.w));
    #pragma unroll
    for (int o = 16; o > 0; o >>= 1) mn = fminf(mn, __shfl_xor_sync(0xffffffffu, mn, o));
    float e0 = __expf(-ALPHA * (v.x - mn));
    float e1 = __expf(-ALPHA * (v.y - mn));
    float e2 = __expf(-ALPHA * (v.z - mn));
    float e3 = __expf(-ALPHA * (v.w - mn));
    float sum = e0 + e1 + e2 + e3;
    #pragma unroll
    for (int o = 16; o > 0; o >>= 1) sum += __shfl_xor_sync(0xffffffffu, sum, o);
    float inv = 1.0f / sum;
    ((float4*)(dout + (size_t)r * CN))[lane] = make_float4(e0*inv, e1*inv, e2*inv, e3*inv);
}

// ---------------------------------------------------------------------------
extern "C" void kernel_launch(void* const* d_in, const int* in_sizes, int n_in,
                              void* d_out, int out_size) {
    const float* x   = (const float*)d_in[0];
    const float* lnw = (const float*)d_in[1];
    const float* lnb = (const float*)d_in[2];
    const float* cc  = (const float*)d_in[3];
    float* out = (float*)d_out;

    const size_t OUT1 = (size_t)BD * C_DIM * CN;   // 4194304

    ln_transpose_kernel<<<dim3(BD, 25), 256>>>(x, lnw, lnb);
    dist_gemm_kernel<<<C_DIM, 256>>>(cc, out, 0);                 // x_distance
    dist_gemm_kernel<<<C_DIM, 256>>>(cc, out + 2 * OUT1, 1);      // cluster_dist
    softmax_kernel<<<BD * C_DIM / 8, 256>>>(out, out + OUT1);     // assign
}

// round 3
// speedup vs baseline: 1.3769x; 1.3769x over previous
#include <cuda_runtime.h>
#include <cuda_bf16.h>
#include <cstdint>

#define C_DIM 256
#define BD    128
#define CN    128
#define KREAL 784
#define KP    832           // padded K (13 * 64)
#define ALPHA 32.0f

// Split bf16 scratch: [C][128][KP] each, hi/lo. 256*128*832/8 uint4 = 54.5MB each
#define NU4 3407872
__device__ uint4 g_xh[NU4];   // layernormed x, hi
__device__ uint4 g_xl[NU4];   // layernormed x, lo
__device__ uint4 g_ch[NU4];   // cluster_center, hi
__device__ uint4 g_cl[NU4];   // cluster_center, lo
__device__ float g_xn[C_DIM * BD];   // |x|^2 per (c, bd)
__device__ float g_cn[C_DIM * CN];   // |cc|^2 per (c, cn)

__device__ __forceinline__ uint32_t smem_u32(const void* p) {
    uint32_t a;
    asm("{ .reg .u64 t; cvta.to.shared.u64 t, %1; cvt.u32.u64 %0, t; }" : "=r"(a) : "l"(p));
    return a;
}

#define SWZ(off) ((off) ^ (((off) >> 3) & 0x70))

#define CP16(dst, src) \
    asm volatile("cp.async.cg.shared.global [%0], [%1], 16;" :: "r"(dst), "l"(src))
#define CP_COMMIT() asm volatile("cp.async.commit_group;" ::: "memory")

#define LDSM4(r0, r1, r2, r3, addr) \
    asm volatile("ldmatrix.sync.aligned.m8n8.x4.shared.b16 {%0,%1,%2,%3}, [%4];" \
                 : "=r"(r0), "=r"(r1), "=r"(r2), "=r"(r3) : "r"(addr))

#define MMA16816(d, a, b) \
    asm volatile("mma.sync.aligned.m16n8k16.row.col.f32.bf16.bf16.f32 " \
                 "{%0,%1,%2,%3},{%4,%5,%6,%7},{%8,%9},{%0,%1,%2,%3};" \
                 : "+f"((d)[0]), "+f"((d)[1]), "+f"((d)[2]), "+f"((d)[3]) \
                 : "r"((a)[0]), "r"((a)[1]), "r"((a)[2]), "r"((a)[3]), \
                   "r"((b)[0]), "r"((b)[1]))

// ---------------------------------------------------------------------------
// Kernel 1: LayerNorm over C + transpose + bf16 hi/lo split + |x|^2 norms.
// One block per bd; loops 26 hw-tiles of 32 (pads K to 832 with zeros).
// ---------------------------------------------------------------------------
__global__ void ln_split_kernel(const float* __restrict__ x,
                                const float* __restrict__ lnw,
                                const float* __restrict__ lnb) {
    __shared__ float s[32][C_DIM + 1];
    int bd   = blockIdx.x;
    int lane = threadIdx.x & 31;
    int warp = threadIdx.x >> 5;
    float nacc[32];
    #pragma unroll
    for (int j = 0; j < 32; j++) nacc[j] = 0.0f;

    __nv_bfloat16* xh = (__nv_bfloat16*)g_xh;
    __nv_bfloat16* xl = (__nv_bfloat16*)g_xl;

    for (int tile = 0; tile < KP / 32; tile++) {
        int hw0 = tile * 32;
        #pragma unroll
        for (int i = 0; i < 4; i++) {
            int p  = warp * 4 + i;
            int hw = hw0 + p;
            int c0 = lane * 4, c1 = 128 + lane * 4;
            if (hw < KREAL) {
                const float4* row = (const float4*)(x + ((size_t)bd * KREAL + hw) * C_DIM);
                float4 v0 = row[lane];
                float4 v1 = row[lane + 32];
                float s1 = v0.x + v0.y + v0.z + v0.w + v1.x + v1.y + v1.z + v1.w;
                float s2 = v0.x*v0.x + v0.y*v0.y + v0.z*v0.z + v0.w*v0.w
                         + v1.x*v1.x + v1.y*v1.y + v1.z*v1.z + v1.w*v1.w;
                #pragma unroll
                for (int o = 16; o > 0; o >>= 1) {
                    s1 += __shfl_xor_sync(0xffffffffu, s1, o);
                    s2 += __shfl_xor_sync(0xffffffffu, s2, o);
                }
                float mean = s1 * (1.0f / C_DIM);
                float var  = s2 * (1.0f / C_DIM) - mean * mean;
                float rs   = rsqrtf(var + 1e-5f);
                s[p][c0+0] = (v0.x - mean) * rs * lnw[c0+0] + lnb[c0+0];
                s[p][c0+1] = (v0.y - mean) * rs * lnw[c0+1] + lnb[c0+1];
                s[p][c0+2] = (v0.z - mean) * rs * lnw[c0+2] + lnb[c0+2];
                s[p][c0+3] = (v0.w - mean) * rs * lnw[c0+3] + lnb[c0+3];
                s[p][c1+0] = (v1.x - mean) * rs * lnw[c1+0] + lnb[c1+0];
                s[p][c1+1] = (v1.y - mean) * rs * lnw[c1+1] + lnb[c1+1];
                s[p][c1+2] = (v1.z - mean) * rs * lnw[c1+2] + lnb[c1+2];
                s[p][c1+3] = (v1.w - mean) * rs * lnw[c1+3] + lnb[c1+3];
            } else {
                #pragma unroll
                for (int e = 0; e < 4; e++) { s[p][c0+e] = 0.0f; s[p][c1+e] = 0.0f; }
            }
        }
        __syncthreads();

        #pragma unroll
        for (int j = 0; j < 32; j++) {
            int c = warp * 32 + j;
            float v = s[lane][c];
            nacc[j] = fmaf(v, v, nacc[j]);
            __nv_bfloat16 h = __float2bfloat16(v);
            __nv_bfloat16 l = __float2bfloat16(v - __bfloat162float(h));
            size_t idx = (size_t)c * (BD * KP) + (size_t)bd * KP + hw0 + lane;
            xh[idx] = h;
            xl[idx] = l;
        }
        __syncthreads();
    }

    // Reduce norms over lanes (each lane holds distinct hw subset for same c).
    #pragma unroll
    for (int j = 0; j < 32; j++) {
        float v = nacc[j];
        #pragma unroll
        for (int o = 16; o > 0; o >>= 1) v += __shfl_xor_sync(0xffffffffu, v, o);
        if (lane == 0) g_xn[(size_t)(warp * 32 + j) * BD + bd] = v;
    }
}

// ---------------------------------------------------------------------------
// Kernel 2: cluster_center fp32 -> bf16 hi/lo split + pad + |cc|^2 norms.
// One block per (c, cn) row.
// ---------------------------------------------------------------------------
__global__ void cc_split_kernel(const float* __restrict__ cc) {
    __shared__ float red[8];
    int row = blockIdx.x;
    int t   = threadIdx.x;
    float ssq = 0.0f;
    if (t < KP / 4) {
        int k0 = t * 4;
        float4 v = make_float4(0.f, 0.f, 0.f, 0.f);
        if (k0 < KREAL)
            v = ((const float4*)(cc + (size_t)row * KREAL))[t];
        ssq = v.x*v.x + v.y*v.y + v.z*v.z + v.w*v.w;

        ushort4 hs, ls;
        float e; __nv_bfloat16 h;
        e = v.x; h = __float2bfloat16(e); hs.x = __bfloat16_as_ushort(h);
        ls.x = __bfloat16_as_ushort(__float2bfloat16(e - __bfloat162float(h)));
        e = v.y; h = __float2bfloat16(e); hs.y = __bfloat16_as_ushort(h);
        ls.y = __bfloat16_as_ushort(__float2bfloat16(e - __bfloat162float(h)));
        e = v.z; h = __float2bfloat16(e); hs.z = __bfloat16_as_ushort(h);
        ls.z = __bfloat16_as_ushort(__float2bfloat16(e - __bfloat162float(h)));
        e = v.w; h = __float2bfloat16(e); hs.w = __bfloat16_as_ushort(h);
        ls.w = __bfloat16_as_ushort(__float2bfloat16(e - __bfloat162float(h)));

        size_t o = (size_t)row * KP + (size_t)k0;
        *(ushort4*)((__nv_bfloat16*)g_ch + o) = hs;
        *(ushort4*)((__nv_bfloat16*)g_cl + o) = ls;
    }
    #pragma unroll
    for (int o = 16; o > 0; o >>= 1) ssq += __shfl_xor_sync(0xffffffffu, ssq, o);
    if ((t & 31) == 0) red[t >> 5] = ssq;
    __syncthreads();
    if (t == 0) {
        float s = 0.f;
        #pragma unroll
        for (int i = 0; i < 8; i++) s += red[i];
        g_cn[row] = s;
    }
}

// ---------------------------------------------------------------------------
// mma.sync distance GEMM. One CTA per batch c; D = 128x128, K = 832 (padded).
// ab = hi*hi + lo*hi + hi*lo (bf16 HMMA, fp32 acc).
// SAME=0: A = cc (m=cn), B = xre (n=bd), out[(n*C + c)*CN + m]
// SAME=1: A = B = cc, out[c*CN*CN + n*CN + m] (symmetric)
// ---------------------------------------------------------------------------
template <int SAME>
__global__ void __launch_bounds__(256, 1)
dist_gemm_mma(float* __restrict__ out) {
    constexpr int AH = 0, AL = 16384;
    constexpr int BH = SAME ? 0 : 32768, BL = SAME ? 16384 : 49152;
    constexpr int STAGE = SAME ? 32768 : 65536;
    constexpr int EPI = (2 * STAGE > 128 * 132 * 4) ? 2 * STAGE : 128 * 132 * 4;

    extern __shared__ char dsm[];
    uint32_t sb0 = smem_u32(dsm);
    uint32_t sbA = (sb0 + 1023u) & ~1023u;
    char* smA = dsm + (sbA - sb0);
    float* sAn = (float*)(smA + EPI);
    float* sBn = sAn + 128;

    int t = threadIdx.x, lane = t & 31, w = t >> 5;
    int c = blockIdx.x;
    int wm = (w >> 1) * 32;       // warp m offset (4 groups)
    int wn = (w & 1) * 64;        // warp n offset (2 groups)

    if (t < 128)      sAn[t] = g_cn[(size_t)c * CN + t];
    else { int n = t - 128; sBn[n] = SAME ? g_cn[(size_t)c * CN + n]
                                          : g_xn[(size_t)c * BD + n]; }

    size_t boff = (size_t)c * 13312;        // 128 rows * 104 uint4
    const uint4* Ahp = g_ch + boff;
    const uint4* Alp = g_cl + boff;
    const uint4* Bhp = SAME ? Ahp : g_xh + boff;
    const uint4* Blp = SAME ? Alp : g_xl + boff;

    auto issue = [&](int kt, int s) {
        uint32_t base = sbA + (uint32_t)s * STAGE;
        #pragma unroll
        for (int j = 0; j < 4; j++) {
            int idx = j * 256 + t;
            int row = idx >> 3, ch = idx & 7;
            size_t go = (size_t)row * 104 + (size_t)kt * 8 + ch;
            uint32_t so = SWZ((uint32_t)idx * 16);
            CP16(base + AH + so, (const void*)(Ahp + go));
            CP16(base + AL + so, (const void*)(Alp + go));
            if (!SAME) {
                CP16(base + BH + so, (const void*)(Bhp + go));
                CP16(base + BL + so, (const void*)(Blp + go));
            }
        }
        CP_COMMIT();
    };

    float acc[2][8][4];
    #pragma unroll
    for (int i = 0; i < 2; i++)
        #pragma unroll
        for (int j = 0; j < 8; j++)
            #pragma unroll
            for (int e = 0; e < 4; e++) acc[i][j][e] = 0.0f;

    issue(0, 0);
    issue(1, 1);

    for (int i = 0; i < 13; i++) {
        if (i < 12) asm volatile("cp.async.wait_group 1;" ::: "memory");
        else        asm volatile("cp.async.wait_group 0;" ::: "memory");
        __syncthreads();

        uint32_t base = sbA + (uint32_t)(i & 1) * STAGE;
        #pragma unroll
        for (int ks = 0; ks < 4; ks++) {
            uint32_t ah[2][4], al[2][4], bb[8][2];
            uint32_t kbA = (uint32_t)ks * 32 + ((lane & 16) ? 16u : 0u);
            uint32_t aA  = base + AH + SWZ((uint32_t)(wm + (lane & 15)) * 128 + kbA);
            LDSM4(ah[0][0], ah[0][1], ah[0][2], ah[0][3], aA);
            LDSM4(ah[1][0], ah[1][1], ah[1][2], ah[1][3], aA + 2048);
            uint32_t aAl = aA + (AL - AH);
            LDSM4(al[0][0], al[0][1], al[0][2], al[0][3], aAl);
            LDSM4(al[1][0], al[1][1], al[1][2], al[1][3], aAl + 2048);

            uint32_t kbB = (uint32_t)ks * 32 + ((lane & 8) ? 16u : 0u);
            uint32_t rB  = (uint32_t)(wn + ((lane & 16) ? 8 : 0) + (lane & 7));
            uint32_t aB  = base + BH + SWZ(rB * 128 + kbB);
            #pragma unroll
            for (int p = 0; p < 4; p++)
                LDSM4(bb[2*p][0], bb[2*p][1], bb[2*p+1][0], bb[2*p+1][1], aB + p * 2048);

            #pragma unroll
            for (int mt = 0; mt < 2; mt++)
                #pragma unroll
                for (int nt = 0; nt < 8; nt++) MMA16816(acc[mt][nt], ah[mt], bb[nt]);
            #pragma unroll
            for (int mt = 0; mt < 2; mt++)
                #pragma unroll
                for (int nt = 0; nt < 8; nt++) MMA16816(acc[mt][nt], al[mt], bb[nt]);

            uint32_t aB2 = aB + (BL - BH);
            #pragma unroll
            for (int p = 0; p < 4; p++)
                LDSM4(bb[2*p][0], bb[2*p][1], bb[2*p+1][0], bb[2*p+1][1], aB2 + p * 2048);
            #pragma unroll
            for (int mt = 0; mt < 2; mt++)
                #pragma unroll
                for (int nt = 0; nt < 8; nt++) MMA16816(acc[mt][nt], ah[mt], bb[nt]);
        }
        __syncthreads();
        if (i + 2 < 13) issue(i + 2, i & 1);
    }

    // Epilogue: d = sqrt(max(an + bn - 2ab, 1e-12)); transpose via smem.
    float* ebuf = (float*)smA;    // [128 n][132 m]
    #pragma unroll
    for (int mt = 0; mt < 2; mt++) {
        #pragma unroll
        for (int nt = 0; nt < 8; nt++) {
            #pragma unroll
            for (int e = 0; e < 4; e++) {
                int m = wm + mt * 16 + (lane >> 2) + ((e >> 1) << 3);
                int n = wn + nt * 8 + ((lane & 3) << 1) + (e & 1);
                float d2 = sAn[m] + sBn[n] - 2.0f * acc[mt][nt][e];
                ebuf[n * 132 + m] = sqrtf(fmaxf(d2, 1e-12f));
            }
        }
    }
    __syncthreads();

    #pragma unroll
    for (int j = 0; j < 16; j++) {
        int idx = j * 256 + t;
        int n = idx >> 5, q = idx & 31;
        float4 v = *(const float4*)&ebuf[n * 132 + q * 4];
        float* dst = SAME
            ? out + (size_t)c * (CN * CN) + (size_t)n * CN + q * 4
            : out + ((size_t)n * C_DIM + (size_t)c) * CN + q * 4;
        *(float4*)dst = v;
    }
}

// ---------------------------------------------------------------------------
// Kernel 4: softmax(-ALPHA * d) over rows of 128. 1 warp / row.
// ---------------------------------------------------------------------------
__global__ void softmax_kernel(const float* __restrict__ din, float* __restrict__ dout) {
    int r    = blockIdx.x * 8 + (threadIdx.x >> 5);
    int lane = threadIdx.x & 31;
    const float4* row = (const float4*)(din + (size_t)r * CN);
    float4 v = row[lane];
    float mn = fminf(fminf(v.x, v.y), fminf(v.z, v.w));
    #pragma unroll
    for (int o = 16; o > 0; o >>= 1) mn = fminf(mn, __shfl_xor_sync(0xffffffffu, mn, o));
    float e0 = __expf(-ALPHA * (v.x - mn));
    float e1 = __expf(-ALPHA * (v.y - mn));
    float e2 = __expf(-ALPHA * (v.z - mn));
    float e3 = __expf(-ALPHA * (v.w - mn));
    float sum = e0 + e1 + e2 + e3;
    #pragma unroll
    for (int o = 16; o > 0; o >>= 1) sum += __shfl_xor_sync(0xffffffffu, sum, o);
    float inv = 1.0f / sum;
    ((float4*)(dout + (size_t)r * CN))[lane] = make_float4(e0*inv, e1*inv, e2*inv, e3*inv);
}

// ---------------------------------------------------------------------------
extern "C" void kernel_launch(void* const* d_in, const int* in_sizes, int n_in,
                              void* d_out, int out_size) {
    const float* x   = (const float*)d_in[0];
    const float* lnw = (const float*)d_in[1];
    const float* lnb = (const float*)d_in[2];
    const float* cc  = (const float*)d_in[3];
    float* out = (float*)d_out;

    const size_t OUT1 = (size_t)BD * C_DIM * CN;       // 4,194,304
    const int SM0 = 2 * 65536 + 1024 + 1024;           // 133,120 B
    const int SM1 = 128 * 132 * 4 + 1024 + 1024;       //  69,632 B

    cudaFuncSetAttribute(dist_gemm_mma<0>, cudaFuncAttributeMaxDynamicSharedMemorySize, SM0);
    cudaFuncSetAttribute(dist_gemm_mma<1>, cudaFuncAttributeMaxDynamicSharedMemorySize, SM1);

    ln_split_kernel<<<BD, 256>>>(x, lnw, lnb);
    cc_split_kernel<<<C_DIM * CN, 256>>>(cc);
    dist_gemm_mma<0><<<C_DIM, 256, SM0>>>(out);                 // x_distance
    dist_gemm_mma<1><<<C_DIM, 256, SM1>>>(out + 2 * OUT1);      // cluster_dist
    softmax_kernel<<<BD * C_DIM / 8, 256>>>(out, out + OUT1);   // assign
}

// round 4
// speedup vs baseline: 1.7829x; 1.2948x over previous
#include <cuda_runtime.h>
#include <cuda_bf16.h>
#include <cstdint>

#define C_DIM 256
#define BD    128
#define CN    128
#define KREAL 784
#define KP    832           // padded K (13 * 64)
#define ALPHA 32.0f

// Split bf16 scratch: [C][128][KP] each, hi/lo. 256*128*832/8 uint4 = 54.5MB each
#define NU4 3407872
__device__ uint4 g_xh[NU4];
__device__ uint4 g_xl[NU4];
__device__ uint4 g_ch[NU4];
__device__ uint4 g_cl[NU4];
__device__ float g_xn[2 * C_DIM * BD];   // |x|^2 partials per (c, bd)
__device__ float g_cn[C_DIM * CN];       // |cc|^2 per (c, cn)
__device__ int   g_ctr;                  // work-queue counter (reset by ln_split)

__device__ __forceinline__ uint32_t smem_u32(const void* p) {
    uint32_t a;
    asm("{ .reg .u64 t; cvta.to.shared.u64 t, %1; cvt.u32.u64 %0, t; }" : "=r"(a) : "l"(p));
    return a;
}

#define SWZ(off) ((off) ^ (((off) >> 3) & 0x70))

#define CP16(dst, src) \
    asm volatile("cp.async.cg.shared.global [%0], [%1], 16;" :: "r"(dst), "l"(src))
#define CP_COMMIT() asm volatile("cp.async.commit_group;" ::: "memory")

#define LDSM4(r0, r1, r2, r3, addr) \
    asm volatile("ldmatrix.sync.aligned.m8n8.x4.shared.b16 {%0,%1,%2,%3}, [%4];" \
                 : "=r"(r0), "=r"(r1), "=r"(r2), "=r"(r3) : "r"(addr))

#define MMA16816(d, a, b) \
    asm volatile("mma.sync.aligned.m16n8k16.row.col.f32.bf16.bf16.f32 " \
                 "{%0,%1,%2,%3},{%4,%5,%6,%7},{%8,%9},{%0,%1,%2,%3};" \
                 : "+f"((d)[0]), "+f"((d)[1]), "+f"((d)[2]), "+f"((d)[3]) \
                 : "r"((a)[0]), "r"((a)[1]), "r"((a)[2]), "r"((a)[3]), \
                   "r"((b)[0]), "r"((b)[1]))

// ---------------------------------------------------------------------------
// Kernel 1: LayerNorm over C + transpose + bf16 hi/lo split + |x|^2 partials.
// grid (BD, 2): part p handles 13 hw-tiles of 32. Wide 16B packed stores.
// ---------------------------------------------------------------------------
__global__ void ln_split_kernel(const float* __restrict__ x,
                                const float* __restrict__ lnw,
                                const float* __restrict__ lnb) {
    __shared__ float s[32][C_DIM + 1];
    int bd   = blockIdx.x;
    int part = blockIdx.y;
    int lane = threadIdx.x & 31;
    int warp = threadIdx.x >> 5;
    if (bd == 0 && part == 0 && threadIdx.x == 0) g_ctr = 0;   // reset work queue

    float nacc[4] = {0.f, 0.f, 0.f, 0.f};
    __nv_bfloat16* xh = (__nv_bfloat16*)g_xh;
    __nv_bfloat16* xl = (__nv_bfloat16*)g_xl;

    for (int tile = part * 13; tile < part * 13 + 13; tile++) {
        int hw0 = tile * 32;
        #pragma unroll
        for (int i = 0; i < 4; i++) {
            int p  = warp * 4 + i;
            int hw = hw0 + p;
            int c0 = lane * 4, c1 = 128 + lane * 4;
            if (hw < KREAL) {
                const float4* row = (const float4*)(x + ((size_t)bd * KREAL + hw) * C_DIM);
                float4 v0 = row[lane];
                float4 v1 = row[lane + 32];
                float s1 = v0.x + v0.y + v0.z + v0.w + v1.x + v1.y + v1.z + v1.w;
                float s2 = v0.x*v0.x + v0.y*v0.y + v0.z*v0.z + v0.w*v0.w
                         + v1.x*v1.x + v1.y*v1.y + v1.z*v1.z + v1.w*v1.w;
                #pragma unroll
                for (int o = 16; o > 0; o >>= 1) {
                    s1 += __shfl_xor_sync(0xffffffffu, s1, o);
                    s2 += __shfl_xor_sync(0xffffffffu, s2, o);
                }
                float mean = s1 * (1.0f / C_DIM);
                float var  = s2 * (1.0f / C_DIM) - mean * mean;
                float rs   = rsqrtf(var + 1e-5f);
                s[p][c0+0] = (v0.x - mean) * rs * lnw[c0+0] + lnb[c0+0];
                s[p][c0+1] = (v0.y - mean) * rs * lnw[c0+1] + lnb[c0+1];
                s[p][c0+2] = (v0.z - mean) * rs * lnw[c0+2] + lnb[c0+2];
                s[p][c0+3] = (v0.w - mean) * rs * lnw[c0+3] + lnb[c0+3];
                s[p][c1+0] = (v1.x - mean) * rs * lnw[c1+0] + lnb[c1+0];
                s[p][c1+1] = (v1.y - mean) * rs * lnw[c1+1] + lnb[c1+1];
                s[p][c1+2] = (v1.z - mean) * rs * lnw[c1+2] + lnb[c1+2];
                s[p][c1+3] = (v1.w - mean) * rs * lnw[c1+3] + lnb[c1+3];
            } else {
                #pragma unroll
                for (int e = 0; e < 4; e++) { s[p][c0+e] = 0.0f; s[p][c1+e] = 0.0f; }
            }
        }
        __syncthreads();

        // Packed store: thread owns (c = warp*32 + pass*8 + lane>>2, 8 hw at (lane&3)*8)
        #pragma unroll
        for (int pass = 0; pass < 4; pass++) {
            int c  = warp * 32 + pass * 8 + (lane >> 2);
            int h0 = (lane & 3) * 8;
            unsigned short hs[8], ls[8];
            #pragma unroll
            for (int h = 0; h < 8; h++) {
                float v = s[h0 + h][c];
                nacc[pass] = fmaf(v, v, nacc[pass]);
                __nv_bfloat16 hb = __float2bfloat16(v);
                hs[h] = __bfloat16_as_ushort(hb);
                ls[h] = __bfloat16_as_ushort(__float2bfloat16(v - __bfloat162float(hb)));
            }
            size_t idx = (size_t)c * (BD * KP) + (size_t)bd * KP + hw0 + h0;
            *(uint4*)(xh + idx) = *(uint4*)hs;
            *(uint4*)(xl + idx) = *(uint4*)ls;
        }
        __syncthreads();
    }

    // Reduce partial norms over the 4 threads (lane&3) sharing each c.
    #pragma unroll
    for (int pass = 0; pass < 4; pass++) {
        float v = nacc[pass];
        v += __shfl_xor_sync(0xffffffffu, v, 1);
        v += __shfl_xor_sync(0xffffffffu, v, 2);
        if ((lane & 3) == 0) {
            int c = warp * 32 + pass * 8 + (lane >> 2);
            g_xn[(size_t)part * (C_DIM * BD) + (size_t)c * BD + bd] = v;
        }
    }
}

// ---------------------------------------------------------------------------
// Kernel 2: cluster_center fp32 -> bf16 hi/lo split + pad + |cc|^2 norms.
// ---------------------------------------------------------------------------
__global__ void cc_split_kernel(const float* __restrict__ cc) {
    __shared__ float red[8];
    int row = blockIdx.x;
    int t   = threadIdx.x;
    float ssq = 0.0f;
    if (t < KP / 4) {
        int k0 = t * 4;
        float4 v = make_float4(0.f, 0.f, 0.f, 0.f);
        if (k0 < KREAL)
            v = ((const float4*)(cc + (size_t)row * KREAL))[t];
        ssq = v.x*v.x + v.y*v.y + v.z*v.z + v.w*v.w;

        ushort4 hs, ls;
        float e; __nv_bfloat16 h;
        e = v.x; h = __float2bfloat16(e); hs.x = __bfloat16_as_ushort(h);
        ls.x = __bfloat16_as_ushort(__float2bfloat16(e - __bfloat162float(h)));
        e = v.y; h = __float2bfloat16(e); hs.y = __bfloat16_as_ushort(h);
        ls.y = __bfloat16_as_ushort(__float2bfloat16(e - __bfloat162float(h)));
        e = v.z; h = __float2bfloat16(e); hs.z = __bfloat16_as_ushort(h);
        ls.z = __bfloat16_as_ushort(__float2bfloat16(e - __bfloat162float(h)));
        e = v.w; h = __float2bfloat16(e); hs.w = __bfloat16_as_ushort(h);
        ls.w = __bfloat16_as_ushort(__float2bfloat16(e - __bfloat162float(h)));

        size_t o = (size_t)row * KP + (size_t)k0;
        *(ushort4*)((__nv_bfloat16*)g_ch + o) = hs;
        *(ushort4*)((__nv_bfloat16*)g_cl + o) = ls;
    }
    #pragma unroll
    for (int o = 16; o > 0; o >>= 1) ssq += __shfl_xor_sync(0xffffffffu, ssq, o);
    if ((t & 31) == 0) red[t >> 5] = ssq;
    __syncthreads();
    if (t == 0) {
        float s = 0.f;
        #pragma unroll
        for (int i = 0; i < 8; i++) s += red[i];
        g_cn[row] = s;
    }
}

// ---------------------------------------------------------------------------
// Persistent merged distance GEMM. Work queue of 1024 slices:
//   ws <  512: x-dist, c = ws>>1, A = cc rows [m0,m0+64), B = x (128 rows)
//   ws >= 512: cc-dist (SAME): A = row-slice OF the B tile (no A load)
// Per slice: D[64 x 128], K = 832, 3-term bf16 split MMA, sqrt epilogue.
// smem: 2 stages x 48KB (AH 8K | AL 8K | BH 16K | BL 16K) + norms. 2 CTAs/SM.
// ---------------------------------------------------------------------------
#define ST_AH 0
#define ST_AL 8192
#define ST_BH 16384
#define ST_BL 32768
#define STAGE 49152
#define NSLICE 1024

__global__ void __launch_bounds__(256, 2)
dist_gemm_all(float* __restrict__ out) {
    extern __shared__ char dsm[];
    __shared__ int s_ws;
    uint32_t sb0 = smem_u32(dsm);
    uint32_t sbA = (sb0 + 1023u) & ~1023u;
    char* smA = dsm + (sbA - sb0);
    float* sAn = (float*)(smA + 2 * STAGE);        // 64 floats
    float* sBn = sAn + 64;                          // 128 floats

    const size_t OUT1 = (size_t)BD * C_DIM * CN;
    int t = threadIdx.x, lane = t & 31, w = t >> 5;
    int wm = (w >> 1) * 16, wn = (w & 1) * 64;

    while (true) {
        if (t == 0) s_ws = atomicAdd(&g_ctr, 1);
        __syncthreads();                            // broadcasts ws; guards stage reuse
        int ws = s_ws;
        if (ws >= NSLICE) break;

        int same = ws >= 512;
        int sl   = same ? ws - 512 : ws;
        int c    = sl >> 1;
        int m0   = (sl & 1) * 64;

        size_t boff = (size_t)c * 13312;            // 128 rows * 104 uint4
        const uint4* Bhp = same ? g_ch + boff : g_xh + boff;
        const uint4* Blp = same ? g_cl + boff : g_xl + boff;
        const uint4* Ahp = g_ch + boff + (size_t)m0 * 104;
        const uint4* Alp = g_cl + boff + (size_t)m0 * 104;

        if (t < 64) sAn[t] = g_cn[(size_t)c * CN + m0 + t];
        else if (t < 192) {
            int n = t - 64;
            sBn[n] = same ? g_cn[(size_t)c * CN + n]
                          : g_xn[(size_t)c * BD + n] + g_xn[C_DIM * BD + (size_t)c * BD + n];
        }

        auto issue = [&](int kt, int s) {
            uint32_t base = sbA + (uint32_t)s * STAGE;
            #pragma unroll
            for (int j = 0; j < 4; j++) {
                int idx = j * 256 + t;
                int row = idx >> 3, ch = idx & 7;
                size_t go = (size_t)row * 104 + (size_t)kt * 8 + ch;
                uint32_t so = SWZ((uint32_t)idx * 16);
                CP16(base + ST_BH + so, (const void*)(Bhp + go));
                CP16(base + ST_BL + so, (const void*)(Blp + go));
            }
            if (!same) {
                #pragma unroll
                for (int j = 0; j < 2; j++) {
                    int idx = j * 256 + t;
                    int row = idx >> 3, ch = idx & 7;
                    size_t go = (size_t)row * 104 + (size_t)kt * 8 + ch;
                    uint32_t so = SWZ((uint32_t)idx * 16);
                    CP16(base + ST_AH + so, (const void*)(Ahp + go));
                    CP16(base + ST_AL + so, (const void*)(Alp + go));
                }
            }
            CP_COMMIT();
        };

        float acc[8][4];
        #pragma unroll
        for (int j = 0; j < 8; j++)
            #pragma unroll
            for (int e = 0; e < 4; e++) acc[j][e] = 0.0f;

        issue(0, 0);
        issue(1, 1);

        uint32_t aoff  = same ? ST_BH : ST_AH;
        uint32_t lodel = same ? (ST_BL - ST_BH) : (ST_AL - ST_AH);
        uint32_t arow  = (same ? m0 : 0) + wm + (lane & 15);

        for (int i = 0; i < 13; i++) {
            if (i < 12) asm volatile("cp.async.wait_group 1;" ::: "memory");
            else        asm volatile("cp.async.wait_group 0;" ::: "memory");
            __syncthreads();

            uint32_t base = sbA + (uint32_t)(i & 1) * STAGE;
            #pragma unroll
            for (int ks = 0; ks < 4; ks++) {
                uint32_t ah[4], al[4], bb[8][2];
                uint32_t kbA = (uint32_t)ks * 32 + ((lane & 16) ? 16u : 0u);
                uint32_t aA  = base + aoff + SWZ(arow * 128 + kbA);
                LDSM4(ah[0], ah[1], ah[2], ah[3], aA);
                LDSM4(al[0], al[1], al[2], al[3], aA + lodel);

                uint32_t kbB = (uint32_t)ks * 32 + ((lane & 8) ? 16u : 0u);
                uint32_t rB  = (uint32_t)(wn + ((lane & 16) ? 8 : 0) + (lane & 7));
                uint32_t aB  = base + ST_BH + SWZ(rB * 128 + kbB);
                #pragma unroll
                for (int p = 0; p < 4; p++)
                    LDSM4(bb[2*p][0], bb[2*p][1], bb[2*p+1][0], bb[2*p+1][1], aB + p * 2048);

                #pragma unroll
                for (int nt = 0; nt < 8; nt++) MMA16816(acc[nt], ah, bb[nt]);
                #pragma unroll
                for (int nt = 0; nt < 8; nt++) MMA16816(acc[nt], al, bb[nt]);

                uint32_t aB2 = aB + (ST_BL - ST_BH);
                #pragma unroll
                for (int p = 0; p < 4; p++)
                    LDSM4(bb[2*p][0], bb[2*p][1], bb[2*p+1][0], bb[2*p+1][1], aB2 + p * 2048);
                #pragma unroll
                for (int nt = 0; nt < 8; nt++) MMA16816(acc[nt], ah, bb[nt]);
            }
            __syncthreads();
            if (i + 2 < 13) issue(i + 2, i & 1);
        }

        // Epilogue: d = sqrt(max(an + bn - 2ab, 1e-12)); transpose via smem.
        float* ebuf = (float*)smA;                  // [128 n][68 m']
        #pragma unroll
        for (int nt = 0; nt < 8; nt++) {
            #pragma unroll
            for (int e = 0; e < 4; e++) {
                int m = wm + (lane >> 2) + ((e >> 1) << 3);
                int n = wn + nt * 8 + ((lane & 3) << 1) + (e & 1);
                float d2 = sAn[m] + sBn[n] - 2.0f * acc[nt][e];
                ebuf[n * 68 + m] = sqrtf(fmaxf(d2, 1e-12f));
            }
        }
        __syncthreads();

        float* obase = same ? out + 2 * OUT1 + (size_t)c * (CN * CN) + m0
                            : out + (size_t)c * CN + m0;
        #pragma unroll
        for (int j = 0; j < 8; j++) {
            int idx = j * 256 + t;
            int n = idx >> 4, q = idx & 15;
            float4 v = *(const float4*)&ebuf[n * 68 + q * 4];
            float* dst = same ? obase + (size_t)n * CN + q * 4
                              : obase + (size_t)n * (C_DIM * CN) + q * 4;
            *(float4*)dst = v;
        }
    }
}

// ---------------------------------------------------------------------------
// Kernel 4: softmax(-ALPHA * d) over rows of 128. 1 warp / row.
// ---------------------------------------------------------------------------
__global__ void softmax_kernel(const float* __restrict__ din, float* __restrict__ dout) {
    int r    = blockIdx.x * 8 + (threadIdx.x >> 5);
    int lane = threadIdx.x & 31;
    const float4* row = (const float4*)(din + (size_t)r * CN);
    float4 v = row[lane];
    float mn = fminf(fminf(v.x, v.y), fminf(v.z, v.w));
    #pragma unroll
    for (int o = 16; o > 0; o >>= 1) mn = fminf(mn, __shfl_xor_sync(0xffffffffu, mn, o));
    float e0 = __expf(-ALPHA * (v.x - mn));
    float e1 = __expf(-ALPHA * (v.y - mn));
    float e2 = __expf(-ALPHA * (v.z - mn));
    float e3 = __expf(-ALPHA * (v.w - mn));
    float sum = e0 + e1 + e2 + e3;
    #pragma unroll
    for (int o = 16; o > 0; o >>= 1) sum += __shfl_xor_sync(0xffffffffu, sum, o);
    float inv = 1.0f / sum;
    ((float4*)(dout + (size_t)r * CN))[lane] = make_float4(e0*inv, e1*inv, e2*inv, e3*inv);
}

// ---------------------------------------------------------------------------
extern "C" void kernel_launch(void* const* d_in, const int* in_sizes, int n_in,
                              void* d_out, int out_size) {
    const float* x   = (const float*)d_in[0];
    const float* lnw = (const float*)d_in[1];
    const float* lnb = (const float*)d_in[2];
    const float* cc  = (const float*)d_in[3];
    float* out = (float*)d_out;

    const size_t OUT1 = (size_t)BD * C_DIM * CN;        // 4,194,304
    const int SMEM = 2 * STAGE + 768 + 1024;            // 100,096 B

    cudaFuncSetAttribute(dist_gemm_all, cudaFuncAttributeMaxDynamicSharedMemorySize, SMEM);

    ln_split_kernel<<<dim3(BD, 2), 256>>>(x, lnw, lnb);
    cc_split_kernel<<<C_DIM * CN, 256>>>(cc);
    dist_gemm_all<<<304, 256, SMEM>>>(out);
    softmax_kernel<<<BD * C_DIM / 8, 256>>>(out, out + OUT1);
}